// round 5
// baseline (speedup 1.0000x reference)
#include <cuda_runtime.h>
#include <math.h>
#include <stdint.h>

#define NSTAGES     5
#define STAGE_ROWS  512      // rows (float4 pairs) per stage per array -> 8 KB each
#define BLOCK       256

// Cross-block reduction scratch (zero at module load; last block re-zeroes).
__device__ double g_sum;
__device__ unsigned int g_done;

struct SmemLayout {
    float4 p[NSTAGES][STAGE_ROWS];   // 5 * 8 KB
    float4 t[NSTAGES][STAGE_ROWS];   // 5 * 8 KB
    unsigned long long full[NSTAGES];
    float warp_sums[8];
};
#define SMEM_BYTES ((int)sizeof(SmemLayout))

__device__ __forceinline__ uint32_t smem_u32(const void* p) {
    uint32_t a;
    asm("{ .reg .u64 t; cvta.to.shared.u64 t, %1; cvt.u32.u64 %0, t; }"
        : "=r"(a) : "l"(p));
    return a;
}
__device__ __forceinline__ void mbar_init(uint32_t a, uint32_t cnt) {
    asm volatile("mbarrier.init.shared.b64 [%0], %1;" :: "r"(a), "r"(cnt) : "memory");
}
__device__ __forceinline__ void mbar_expect_tx(uint32_t a, uint32_t bytes) {
    asm volatile("mbarrier.arrive.expect_tx.shared.b64 _, [%0], %1;"
                 :: "r"(a), "r"(bytes) : "memory");
}
__device__ __forceinline__ void mbar_wait(uint32_t a, uint32_t parity) {
    asm volatile(
        "{\n\t.reg .pred P;\n"
        "W%=:\n\t"
        "mbarrier.try_wait.parity.shared.b64 P, [%0], %1;\n\t"
        "@!P bra W%=;\n\t}"
        :: "r"(a), "r"(parity) : "memory");
}
__device__ __forceinline__ void bulk_g2s(uint32_t dst, const void* src,
                                         uint32_t bytes, uint32_t mbar) {
    asm volatile(
        "cp.async.bulk.shared::cta.global.mbarrier::complete_tx::bytes "
        "[%0], [%1], %2, [%3];"
        :: "r"(dst), "l"(src), "r"(bytes), "r"(mbar) : "memory");
}

__device__ __forceinline__ float row_loss(float4 p, float4 t)
{
    const float DELTA = 0.1f;
    const float inv3  = 1.0f / 3.0f;

    float mp = (p.x + p.y + p.z + p.w) * 0.25f;
    float mt = (t.x + t.y + t.z + t.w) * 0.25f;

    float dpx = p.x - mp, dpy = p.y - mp, dpz = p.z - mp, dpw = p.w - mp;
    float dtx = t.x - mt, dty = t.y - mt, dtz = t.z - mt, dtw = t.w - mt;

    float var_p = (dpx*dpx + dpy*dpy + dpz*dpz + dpw*dpw) * inv3;
    float var_t = (dtx*dtx + dty*dty + dtz*dtz + dtw*dtw) * inv3;
    float cov   = (dpx*dtx + dpy*dty + dpz*dtz + dpw*dtw) * inv3;

    float a1 = 2.0f * mp * mt + DELTA;
    float a2 = 2.0f * cov + DELTA;
    float b1 = mp * mp + mt * mt + DELTA;
    float b2 = var_p + var_t + DELTA;

    // __fdividef: rcp.approx + mul (2 instrs vs ~12). rel tolerance is 1e-3;
    // operands are O(1), so 2-ulp approx error is ~1e-7 — negligible.
    return 1.0f - __fdividef(a1 * a2, b1 * b2 + DELTA);
}

__global__ void __launch_bounds__(BLOCK, 2)
ssim_loss_tma_kernel(const float4* __restrict__ pred,
                     const float4* __restrict__ target,
                     float* __restrict__ out,
                     int n_rows)
{
    extern __shared__ unsigned char smem_raw[];
    SmemLayout* sm = (SmemLayout*)smem_raw;

    const int tid = threadIdx.x;
    const int total_chunks = (n_rows + STAGE_ROWS - 1) / STAGE_ROWS;

    // Chunks for this CTA: c_n = blockIdx.x + n*gridDim.x, n = 0..my_chunks-1
    int my_chunks = 0;
    if ((int)blockIdx.x < total_chunks)
        my_chunks = (total_chunks - blockIdx.x + gridDim.x - 1) / gridDim.x;

    uint32_t full_addr[NSTAGES];
    #pragma unroll
    for (int s = 0; s < NSTAGES; s++)
        full_addr[s] = smem_u32(&sm->full[s]);

    if (tid == 0) {
        #pragma unroll
        for (int s = 0; s < NSTAGES; s++)
            mbar_init(full_addr[s], 1);
        // fence so TMA engine (async proxy) observes the init
        asm volatile("fence.proxy.async.shared::cta;" ::: "memory");
    }
    __syncthreads();

    // Prologue: fill the pipeline
    if (tid == 0) {
        int pro = my_chunks < NSTAGES ? my_chunks : NSTAGES;
        for (int n = 0; n < pro; n++) {
            int c = blockIdx.x + n * gridDim.x;
            int rows = n_rows - c * STAGE_ROWS;
            if (rows > STAGE_ROWS) rows = STAGE_ROWS;
            uint32_t bytes = (uint32_t)rows * 16u;
            mbar_expect_tx(full_addr[n], 2u * bytes);
            bulk_g2s(smem_u32(&sm->p[n][0]), pred   + (size_t)c * STAGE_ROWS, bytes, full_addr[n]);
            bulk_g2s(smem_u32(&sm->t[n][0]), target + (size_t)c * STAGE_ROWS, bytes, full_addr[n]);
        }
    }

    float local = 0.0f;

    for (int n = 0; n < my_chunks; n++) {
        int s  = n % NSTAGES;
        int ph = (n / NSTAGES) & 1;
        mbar_wait(full_addr[s], ph);

        int c = blockIdx.x + n * gridDim.x;
        int rows = n_rows - c * STAGE_ROWS;
        if (rows > STAGE_ROWS) rows = STAGE_ROWS;

        // Conflict-free: thread t reads rows t and t+256 (contiguous per warp).
        if (tid < rows)
            local += row_loss(sm->p[s][tid], sm->t[s][tid]);
        if (tid + BLOCK < rows)
            local += row_loss(sm->p[s][tid + BLOCK], sm->t[s][tid + BLOCK]);

        __syncthreads();   // all reads of stage s done before refill

        if (tid == 0) {
            int nn = n + NSTAGES;
            if (nn < my_chunks) {
                int cc = blockIdx.x + nn * gridDim.x;
                int rr = n_rows - cc * STAGE_ROWS;
                if (rr > STAGE_ROWS) rr = STAGE_ROWS;
                uint32_t bytes = (uint32_t)rr * 16u;
                mbar_expect_tx(full_addr[s], 2u * bytes);
                bulk_g2s(smem_u32(&sm->p[s][0]), pred   + (size_t)cc * STAGE_ROWS, bytes, full_addr[s]);
                bulk_g2s(smem_u32(&sm->t[s][0]), target + (size_t)cc * STAGE_ROWS, bytes, full_addr[s]);
            }
        }
    }

    // Warp reduction
    #pragma unroll
    for (int off = 16; off > 0; off >>= 1)
        local += __shfl_down_sync(0xFFFFFFFFu, local, off);

    int lane = tid & 31;
    int wid  = tid >> 5;
    if (lane == 0) sm->warp_sums[wid] = local;
    __syncthreads();

    if (wid == 0) {
        float bs = (lane < 8) ? sm->warp_sums[lane] : 0.0f;
        #pragma unroll
        for (int off = 4; off > 0; off >>= 1)
            bs += __shfl_down_sync(0xFFFFFFFFu, bs, off);

        if (lane == 0) {
            atomicAdd(&g_sum, (double)bs);
            __threadfence();
            unsigned int prev = atomicAdd(&g_done, 1u);
            if (prev == gridDim.x - 1) {
                double mean = g_sum / (double)n_rows;
                float r = (float)mean;
                if (isnan(r)) r = 1.0f;   // reference NaN fallback == 1.0
                out[0] = r;
                g_sum = 0.0;
                g_done = 0u;
                __threadfence();
            }
        }
    }
}

extern "C" void kernel_launch(void* const* d_in, const int* in_sizes, int n_in,
                              void* d_out, int out_size)
{
    const float4* pred   = (const float4*)d_in[0];
    const float4* target = (const float4*)d_in[1];
    float* out = (float*)d_out;

    int n_rows = in_sizes[0] / 4;   // [N, 4] float32 -> N rows of float4

    static int attr_set = 0;
    if (!attr_set) {
        cudaFuncSetAttribute(ssim_loss_tma_kernel,
                             cudaFuncAttributeMaxDynamicSharedMemorySize,
                             SMEM_BYTES);
        attr_set = 1;
    }

    int total_chunks = (n_rows + STAGE_ROWS - 1) / STAGE_ROWS;
    int blocks = 148 * 2;           // 2 CTAs/SM, 160 KB smem in flight per SM
    if (blocks > total_chunks) blocks = total_chunks;

    ssim_loss_tma_kernel<<<blocks, BLOCK, SMEM_BYTES>>>(pred, target, out, n_rows);
}